// round 4
// baseline (speedup 1.0000x reference)
#include <cuda_runtime.h>
#include <cuda_bf16.h>
#include <cstdint>

// TELIF: temporal-encoded LIF spiking neuron scan.
// tx: [T, B, N] f32, TE: [N, T] f32 -> ty: [T, B, N] f32.
//
// R4: cp.async (LDGSTS) smem pipeline. Register-resident prefetch capped DRAM
// at ~45% for three rounds (compute chain runs with no loads outstanding;
// ptxas won't keep deep register batches hoisted). cp.async decouples load
// issue from registers: 4-stage ring, wait_group 2 keeps 3 chunks (24KB/SM)
// perpetually in flight while the serial LIF chain runs out of smem.

#define T_STEPS 512
#define B_DIM   64
#define N_DIM   1024
#define BN      (B_DIM * N_DIM)

#define REST      0.0f
#define DECAY     0.2f
#define THRESHOLD 0.3f
#define BETA      0.02f

#define BLK       64                 // threads per block (2 warps)
#define CHUNK     8                  // time steps per pipeline stage
#define STAGES    4
#define NCHUNK    (T_STEPS / CHUNK)  // 64
#define STAGE_F   (CHUNK * BLK)      // floats per stage per array (512)

__device__ float g_te_t[T_STEPS * N_DIM];  // TE transposed to [T][N]

// ---------------------------------------------------------------------------
// Transpose TE [N, T] -> g_te_t [T, N]. 32x32 tiles, padded smem.
// ---------------------------------------------------------------------------
__global__ void telif_transpose_te(const float* __restrict__ TE) {
    __shared__ float tile[32][33];
    int n0 = blockIdx.x * 32;
    int t0 = blockIdx.y * 32;
    int lx = threadIdx.x;
    int ly = threadIdx.y;

#pragma unroll
    for (int i = 0; i < 32; i += 8)
        tile[ly + i][lx] = TE[(size_t)(n0 + ly + i) * T_STEPS + (t0 + lx)];
    __syncthreads();
#pragma unroll
    for (int i = 0; i < 32; i += 8)
        g_te_t[(size_t)(t0 + ly + i) * N_DIM + (n0 + lx)] = tile[lx][ly + i];
}

// ---------------------------------------------------------------------------
// cp.async helpers
// ---------------------------------------------------------------------------
__device__ __forceinline__ void cp_async16(uint32_t smem_addr, const void* gptr) {
    asm volatile("cp.async.ca.shared.global [%0], [%1], 16;\n"
                 :: "r"(smem_addr), "l"(gptr));
}
__device__ __forceinline__ void cp_commit() {
    asm volatile("cp.async.commit_group;\n");
}
__device__ __forceinline__ void cp_wait2() {
    asm volatile("cp.async.wait_group 2;\n" ::: "memory");
}

// ---------------------------------------------------------------------------
// Main scan. One thread per (b, n). 4-stage cp.async pipeline.
// ---------------------------------------------------------------------------
__global__ void __launch_bounds__(BLK)
telif_scan(const float* __restrict__ tx, float* __restrict__ out) {
    __shared__ float sm_tx[STAGES][STAGE_F];
    __shared__ float sm_te[STAGES][STAGE_F];

    const int tid  = threadIdx.x;
    const int base = blockIdx.x * BLK;      // first (b*N+n) lane of this block
    const int idx  = base + tid;
    const int n0   = base & (N_DIM - 1);    // block's first n (contiguous 64)

    const float* txb = tx + base;           // row base for this block
    const float* teb = g_te_t + n0;
    float*       op  = out + idx;

    // Issue one stage's copies for chunk c into buffer (c % STAGES).
    // Chunk covers time steps [c*CHUNK, c*CHUNK+CHUNK).
    // 16B chunk k (k in {tid, tid+BLK}): step s = k/16, lane4 = (k%16)*4.
    // Each 16-thread group copies one contiguous 256B row segment (coalesced).
    auto issue = [&](int c) {
        const int buf = c & (STAGES - 1);
        const float* stx = txb + (size_t)(c * CHUNK) * BN;
        const float* ste = teb + (size_t)(c * CHUNK) * N_DIM;
        uint32_t sx = (uint32_t)__cvta_generic_to_shared(&sm_tx[buf][0]);
        uint32_t se = (uint32_t)__cvta_generic_to_shared(&sm_te[buf][0]);
#pragma unroll
        for (int j = 0; j < 2; j++) {
            int k     = tid + j * BLK;
            int s     = k >> 4;
            int lane4 = (k & 15) * 4;
            int soff  = (s * BLK + lane4) * 4;
            cp_async16(sx + soff, stx + (size_t)s * BN + lane4);
            cp_async16(se + soff, ste + (size_t)s * N_DIM + lane4);
        }
    };

    // Prologue: fill STAGES-1 buffers.
#pragma unroll
    for (int c = 0; c < STAGES - 1; c++) {
        issue(c);
        cp_commit();
    }

    float v  = REST;
    float y  = 0.0f;
    float th = THRESHOLD;

#pragma unroll 1
    for (int c = 0; c < NCHUNK; c++) {
        cp_wait2();                 // chunk c's group complete
        __syncthreads();            // make all threads' copies visible;
                                    // also guards buffer reuse below

        if (c + STAGES - 1 < NCHUNK) issue(c + STAGES - 1);
        cp_commit();                // commit every iter (uniform group count)

        const int buf = c & (STAGES - 1);
        const float* ltx = &sm_tx[buf][tid];
        const float* lte = &sm_te[buf][tid];
#pragma unroll
        for (int s = 0; s < CHUNK; s++) {
            float te = lte[s * BLK];
            float x  = ltx[s * BLK];
            th = th + v * te - (th - THRESHOLD) * BETA;
            v  = v * DECAY * (1.0f - y) + x;
            y  = (v > th) ? 1.0f : 0.0f;
            op[(size_t)(c * CHUNK + s) * BN] = y;
        }
    }
}

// ---------------------------------------------------------------------------
// Launch
// ---------------------------------------------------------------------------
extern "C" void kernel_launch(void* const* d_in, const int* in_sizes, int n_in,
                              void* d_out, int out_size) {
    const float* tx = (const float*)d_in[0];   // [T, B, N]
    const float* TE = (const float*)d_in[1];   // [N, T]
    float* out = (float*)d_out;                // [T, B, N]

    (void)in_sizes; (void)n_in; (void)out_size;

    dim3 tb(32, 8);
    dim3 tg(N_DIM / 32, T_STEPS / 32);
    telif_transpose_te<<<tg, tb>>>(TE);

    telif_scan<<<BN / BLK, BLK>>>(tx, out);
}